// round 1
// baseline (speedup 1.0000x reference)
#include <cuda_runtime.h>
#include <math.h>

#define Dm 1024
#define NH 16
#define HD 64
#define BB 2
#define SEQ 2048
#define MROWS (BB*SEQ)   // 4096

// Scratch (alloc-free rule: __device__ globals)
__device__ float g_Q[MROWS*Dm];
__device__ float g_K[MROWS*Dm];
__device__ float g_V[MROWS*Dm];
__device__ float g_A[MROWS*Dm];
__device__ float g_Y[MROWS*Dm];

// ---------------------------------------------------------------------------
// C[m,n] = bias[n] + sum_k A[m,k]*W[n,k]  (+ res[m,n])
// A: [Mr,K] row-major, W: [Nc,K] row-major (both K-contiguous -> NT GEMM)
// 64x64 block tile, BK=16, 256 threads, 4x4 per thread.
// ---------------------------------------------------------------------------
template<bool HAS_RES>
__global__ __launch_bounds__(256) void gemm_bias_kernel(
    const float* __restrict__ A, const float* __restrict__ W,
    const float* __restrict__ bias, const float* __restrict__ res,
    float* __restrict__ C, int Mr, int Nc, int K)
{
    __shared__ float As[16][68];
    __shared__ float Bs[16][68];
    const int bm = blockIdx.y * 64;
    const int bn = blockIdx.x * 64;
    const int tid = threadIdx.x;
    const int tx = tid & 15, ty = tid >> 4;
    const int lrow = tid >> 2;          // 0..63
    const int lc4  = (tid & 3) << 2;    // 0,4,8,12

    const float* Ap = A + (size_t)(bm + lrow) * K + lc4;
    const float* Wp = W + (size_t)(bn + lrow) * K + lc4;

    float acc[4][4] = {};

    for (int k0 = 0; k0 < K; k0 += 16) {
        float4 av = *(const float4*)(Ap + k0);
        float4 wv = *(const float4*)(Wp + k0);
        As[lc4+0][lrow] = av.x; As[lc4+1][lrow] = av.y;
        As[lc4+2][lrow] = av.z; As[lc4+3][lrow] = av.w;
        Bs[lc4+0][lrow] = wv.x; Bs[lc4+1][lrow] = wv.y;
        Bs[lc4+2][lrow] = wv.z; Bs[lc4+3][lrow] = wv.w;
        __syncthreads();
        #pragma unroll
        for (int kk = 0; kk < 16; kk++) {
            float a[4], b[4];
            #pragma unroll
            for (int i = 0; i < 4; i++) a[i] = As[kk][ty*4 + i];
            #pragma unroll
            for (int j = 0; j < 4; j++) b[j] = Bs[kk][tx*4 + j];
            #pragma unroll
            for (int i = 0; i < 4; i++)
                #pragma unroll
                for (int j = 0; j < 4; j++)
                    acc[i][j] = fmaf(a[i], b[j], acc[i][j]);
        }
        __syncthreads();
    }

    const int cbase = bn + tx*4;
    float4 bv = *(const float4*)(bias + cbase);
    #pragma unroll
    for (int i = 0; i < 4; i++) {
        int r = bm + ty*4 + i;
        float4 o;
        o.x = acc[i][0] + bv.x;
        o.y = acc[i][1] + bv.y;
        o.z = acc[i][2] + bv.z;
        o.w = acc[i][3] + bv.w;
        if (HAS_RES) {
            float4 rv = *(const float4*)(res + (size_t)r * Nc + cbase);
            o.x += rv.x; o.y += rv.y; o.z += rv.z; o.w += rv.w;
        }
        *(float4*)(C + (size_t)r * Nc + cbase) = o;
    }
}

// ---------------------------------------------------------------------------
// Flash attention (fp32, online softmax).
// Block: 64 queries of one (b,h); loop over 32 KV tiles of 64.
// 256 threads in 16x16; each thread owns a 4x4 micro-tile.
// ---------------------------------------------------------------------------
__global__ __launch_bounds__(256) void attn_kernel(const float* __restrict__ ascale)
{
    extern __shared__ float sm[];
    float* Qs = sm;                 // [64][68]
    float* Ks = sm + 64*68;        // [64][68]
    float* Vs = sm + 2*64*68;      // [64][68]
    float* Ps = sm + 3*64*68;      // [64][68]

    const int q0 = blockIdx.x * 64;
    const int h  = blockIdx.y;
    const int b  = blockIdx.z;
    const int tid = threadIdx.x;
    const int tx = tid & 15, ty = tid >> 4;

    const float sc = ascale[h] * 0.125f;   // HD^-0.5 = 0.125, TEMP = 1

    // Load Q tile: 64 rows x 64 cols
    #pragma unroll
    for (int t = 0; t < 4; t++) {
        int idx = tid + t*256;            // 0..1023 (float4 units)
        int row = idx >> 4;
        int c4  = (idx & 15) << 2;
        float4 v = *(const float4*)(g_Q + (size_t)(b*SEQ + q0 + row)*Dm + h*HD + c4);
        Qs[row*68 + c4+0] = v.x; Qs[row*68 + c4+1] = v.y;
        Qs[row*68 + c4+2] = v.z; Qs[row*68 + c4+3] = v.w;
    }

    float m[4], l[4], acc[4][4];
    #pragma unroll
    for (int i = 0; i < 4; i++) {
        m[i] = -INFINITY; l[i] = 0.f;
        #pragma unroll
        for (int j = 0; j < 4; j++) acc[i][j] = 0.f;
    }

    for (int k0 = 0; k0 < SEQ; k0 += 64) {
        // Load K and V tiles
        #pragma unroll
        for (int t = 0; t < 4; t++) {
            int idx = tid + t*256;
            int row = idx >> 4;
            int c4  = (idx & 15) << 2;
            size_t off = (size_t)(b*SEQ + k0 + row)*Dm + h*HD + c4;
            float4 kv = *(const float4*)(g_K + off);
            float4 vv = *(const float4*)(g_V + off);
            Ks[row*68 + c4+0] = kv.x; Ks[row*68 + c4+1] = kv.y;
            Ks[row*68 + c4+2] = kv.z; Ks[row*68 + c4+3] = kv.w;
            Vs[row*68 + c4+0] = vv.x; Vs[row*68 + c4+1] = vv.y;
            Vs[row*68 + c4+2] = vv.z; Vs[row*68 + c4+3] = vv.w;
        }
        __syncthreads();

        // S = Q @ K^T (4x4 per thread)
        float s[4][4] = {};
        #pragma unroll 16
        for (int d = 0; d < 64; d++) {
            float a[4], bb[4];
            #pragma unroll
            for (int i = 0; i < 4; i++) a[i]  = Qs[(ty*4 + i)*68 + d];
            #pragma unroll
            for (int j = 0; j < 4; j++) bb[j] = Ks[(tx*4 + j)*68 + d];
            #pragma unroll
            for (int i = 0; i < 4; i++)
                #pragma unroll
                for (int j = 0; j < 4; j++)
                    s[i][j] = fmaf(a[i], bb[j], s[i][j]);
        }

        // Online softmax per query row (reduce across the 16 tx lanes)
        #pragma unroll
        for (int i = 0; i < 4; i++) {
            #pragma unroll
            for (int j = 0; j < 4; j++) s[i][j] *= sc;
            float rm = fmaxf(fmaxf(s[i][0], s[i][1]), fmaxf(s[i][2], s[i][3]));
            #pragma unroll
            for (int off = 8; off; off >>= 1)
                rm = fmaxf(rm, __shfl_xor_sync(0xffffffffu, rm, off));
            float mn = fmaxf(m[i], rm);
            float corr = __expf(m[i] - mn);
            float rs = 0.f;
            #pragma unroll
            for (int j = 0; j < 4; j++) {
                float p = __expf(s[i][j] - mn);
                s[i][j] = p;
                rs += p;
            }
            #pragma unroll
            for (int off = 8; off; off >>= 1)
                rs += __shfl_xor_sync(0xffffffffu, rs, off);
            l[i] = l[i] * corr + rs;
            m[i] = mn;
            #pragma unroll
            for (int j = 0; j < 4; j++) acc[i][j] *= corr;
            #pragma unroll
            for (int j = 0; j < 4; j++)
                Ps[(ty*4 + i)*68 + tx*4 + j] = s[i][j];
        }
        __syncthreads();

        // O += P @ V
        #pragma unroll 16
        for (int k = 0; k < 64; k++) {
            float a[4], bb[4];
            #pragma unroll
            for (int i = 0; i < 4; i++) a[i]  = Ps[(ty*4 + i)*68 + k];
            #pragma unroll
            for (int j = 0; j < 4; j++) bb[j] = Vs[k*68 + tx*4 + j];
            #pragma unroll
            for (int i = 0; i < 4; i++)
                #pragma unroll
                for (int j = 0; j < 4; j++)
                    acc[i][j] = fmaf(a[i], bb[j], acc[i][j]);
        }
        __syncthreads();
    }

    // Write O / l to attn buffer in [B,N,H*HD] layout
    #pragma unroll
    for (int i = 0; i < 4; i++) {
        float inv = 1.f / l[i];
        int row = q0 + ty*4 + i;
        int col = h*HD + tx*4;
        float4 o;
        o.x = acc[i][0]*inv; o.y = acc[i][1]*inv;
        o.z = acc[i][2]*inv; o.w = acc[i][3]*inv;
        *(float4*)(g_A + (size_t)(b*SEQ + row)*Dm + col) = o;
    }
}

// ---------------------------------------------------------------------------
// LayerNorm: one block per row, 256 threads x 4 elems.
// ---------------------------------------------------------------------------
__global__ __launch_bounds__(256) void ln_kernel(
    const float* __restrict__ y, const float* __restrict__ gamma,
    const float* __restrict__ beta, float* __restrict__ out)
{
    __shared__ float red[16];
    __shared__ float mu_s, rstd_s;
    const int row = blockIdx.x;
    const int tid = threadIdx.x;
    const float* yr = y + (size_t)row * Dm;

    float4 v = *(const float4*)(yr + tid*4);
    float s  = v.x + v.y + v.z + v.w;
    float s2 = v.x*v.x + v.y*v.y + v.z*v.z + v.w*v.w;
    #pragma unroll
    for (int off = 16; off; off >>= 1) {
        s  += __shfl_xor_sync(0xffffffffu, s,  off);
        s2 += __shfl_xor_sync(0xffffffffu, s2, off);
    }
    if ((tid & 31) == 0) {
        red[tid >> 5] = s;
        red[8 + (tid >> 5)] = s2;
    }
    __syncthreads();
    if (tid == 0) {
        float S = 0.f, S2 = 0.f;
        #pragma unroll
        for (int w = 0; w < 8; w++) { S += red[w]; S2 += red[8 + w]; }
        float mu = S * (1.f/1024.f);
        float var = S2 * (1.f/1024.f) - mu*mu;
        mu_s = mu;
        rstd_s = rsqrtf(var + 1e-5f);
    }
    __syncthreads();
    const float mu = mu_s, rstd = rstd_s;
    float4 g  = *(const float4*)(gamma + tid*4);
    float4 be = *(const float4*)(beta  + tid*4);
    float4 o;
    o.x = (v.x - mu) * rstd * g.x + be.x;
    o.y = (v.y - mu) * rstd * g.y + be.y;
    o.z = (v.z - mu) * rstd * g.z + be.z;
    o.w = (v.w - mu) * rstd * g.w + be.w;
    *(float4*)(out + (size_t)row * Dm + tid*4) = o;
}

// ---------------------------------------------------------------------------
extern "C" void kernel_launch(void* const* d_in, const int* in_sizes, int n_in,
                              void* d_out, int out_size)
{
    const float* x     = (const float*)d_in[0];
    const float* as    = (const float*)d_in[1];
    const float* Wq    = (const float*)d_in[2];
    const float* bq    = (const float*)d_in[3];
    const float* Wk    = (const float*)d_in[4];
    const float* bk    = (const float*)d_in[5];
    const float* Wv    = (const float*)d_in[6];
    const float* bv    = (const float*)d_in[7];
    const float* Wo    = (const float*)d_in[8];
    const float* bo    = (const float*)d_in[9];
    const float* gamma = (const float*)d_in[10];
    const float* beta  = (const float*)d_in[11];
    float* out = (float*)d_out;

    float *Qp, *Kp, *Vp, *Ap, *Yp;
    cudaGetSymbolAddress((void**)&Qp, g_Q);
    cudaGetSymbolAddress((void**)&Kp, g_K);
    cudaGetSymbolAddress((void**)&Vp, g_V);
    cudaGetSymbolAddress((void**)&Ap, g_A);
    cudaGetSymbolAddress((void**)&Yp, g_Y);

    dim3 blk(256);
    dim3 gg(Dm/64, MROWS/64);   // (16, 64)

    gemm_bias_kernel<false><<<gg, blk>>>(x,  Wq, bq, nullptr, Qp, MROWS, Dm, Dm);
    gemm_bias_kernel<false><<<gg, blk>>>(x,  Wk, bk, nullptr, Kp, MROWS, Dm, Dm);
    gemm_bias_kernel<false><<<gg, blk>>>(x,  Wv, bv, nullptr, Vp, MROWS, Dm, Dm);

    size_t smem = 4 * 64 * 68 * sizeof(float);   // 69632 B
    cudaFuncSetAttribute(attn_kernel, cudaFuncAttributeMaxDynamicSharedMemorySize, (int)smem);
    attn_kernel<<<dim3(SEQ/64, NH, BB), blk, smem>>>(as);

    gemm_bias_kernel<true><<<gg, blk>>>(Ap, Wo, bo, x, Yp, MROWS, Dm, Dm);

    ln_kernel<<<MROWS, blk>>>(Yp, gamma, beta, out);
}

// round 4
// speedup vs baseline: 1.2248x; 1.2248x over previous
#include <cuda_runtime.h>
#include <cuda_bf16.h>
#include <cstdint>
#include <math.h>

#define Dm 1024
#define NH 16
#define HD 64
#define BB 2
#define SEQ 2048
#define MROWS (BB*SEQ)   // 4096
#define KCAT 2048        // [hi | lo] concatenated K

// Scratch (alloc-free rule: __device__ globals)
__device__ float g_Q[MROWS*Dm];
__device__ float g_K[MROWS*Dm];
__device__ float g_V[MROWS*Dm];
__device__ float g_A[MROWS*Dm];
__device__ float g_Y[MROWS*Dm];
__device__ __nv_bfloat16 g_Xcat[(size_t)MROWS*KCAT];
__device__ __nv_bfloat16 g_Acat[(size_t)MROWS*KCAT];
__device__ __nv_bfloat16 g_Wcat[4][(size_t)Dm*KCAT];

__device__ __forceinline__ uint32_t s2u(const void* p) {
    uint32_t a;
    asm("{ .reg .u64 t; cvta.to.shared.u64 t, %1; cvt.u32.u64 %0, t; }" : "=r"(a) : "l"(p));
    return a;
}

// ---------------------------------------------------------------------------
// split fp32 -> [bf16 hi | bf16 lo] concatenated along K
// ---------------------------------------------------------------------------
__global__ __launch_bounds__(256) void split_kernel(
    const float* __restrict__ src, __nv_bfloat16* __restrict__ dst, int nrows)
{
    int idx = blockIdx.x * 256 + threadIdx.x;      // float4 units
    int total = nrows * (Dm / 4);
    if (idx >= total) return;
    int r  = idx / (Dm / 4);
    int c  = (idx % (Dm / 4)) * 4;
    float4 v = *(const float4*)(src + (size_t)r * Dm + c);
    __nv_bfloat16 h0 = __float2bfloat16(v.x);
    __nv_bfloat16 h1 = __float2bfloat16(v.y);
    __nv_bfloat16 h2 = __float2bfloat16(v.z);
    __nv_bfloat16 h3 = __float2bfloat16(v.w);
    __nv_bfloat16 l0 = __float2bfloat16(v.x - __bfloat162float(h0));
    __nv_bfloat16 l1 = __float2bfloat16(v.y - __bfloat162float(h1));
    __nv_bfloat16 l2 = __float2bfloat16(v.z - __bfloat162float(h2));
    __nv_bfloat16 l3 = __float2bfloat16(v.w - __bfloat162float(h3));
    __nv_bfloat162* dh = (__nv_bfloat162*)(dst + (size_t)r * KCAT + c);
    __nv_bfloat162* dl = (__nv_bfloat162*)(dst + (size_t)r * KCAT + Dm + c);
    dh[0] = __nv_bfloat162(h0, h1);
    dh[1] = __nv_bfloat162(h2, h3);
    dl[0] = __nv_bfloat162(l0, l1);
    dl[1] = __nv_bfloat162(l2, l3);
}

// ---------------------------------------------------------------------------
// HMMA (mma.sync m16n8k16 bf16) GEMM:
// C[4096,1024] = bias + sum over 3 hi/lo segments of Acat @ Bcat^T  (+ res)
// 128x128 CTA tile, 8 warps of 64x32, BK=64.
// ---------------------------------------------------------------------------
#define LDMAT4(r0,r1,r2,r3,addr) \
    asm volatile("ldmatrix.sync.aligned.m8n8.x4.shared.b16 {%0,%1,%2,%3}, [%4];" \
        : "=r"(r0),"=r"(r1),"=r"(r2),"=r"(r3) : "r"(addr))

#define MMA16816(c0,c1,c2,c3,a0,a1,a2,a3,b0,b1) \
    asm volatile("mma.sync.aligned.m16n8k16.row.col.f32.bf16.bf16.f32 " \
        "{%0,%1,%2,%3}, {%4,%5,%6,%7}, {%8,%9}, {%0,%1,%2,%3};" \
        : "+f"(c0),"+f"(c1),"+f"(c2),"+f"(c3) \
        : "r"(a0),"r"(a1),"r"(a2),"r"(a3),"r"(b0),"r"(b1))

template<bool HAS_RES>
__global__ __launch_bounds__(256) void hmma_gemm(
    const __nv_bfloat16* __restrict__ Acat, const __nv_bfloat16* __restrict__ Bcat,
    const float* __restrict__ bias, const float* __restrict__ res,
    float* __restrict__ C)
{
    __shared__ __align__(16) __nv_bfloat16 As[128][72];
    __shared__ __align__(16) __nv_bfloat16 Bs[128][72];

    const int tid  = threadIdx.x;
    const int wid  = tid >> 5, lane = tid & 31;
    const int bm = blockIdx.y * 128;
    const int bn = blockIdx.x * 128;
    const int wm = (wid >> 2) * 64;     // warp row offset within tile
    const int wn = (wid & 3) * 32;      // warp col offset within tile

    float c[4][4][4];
    #pragma unroll
    for (int i = 0; i < 4; i++)
        #pragma unroll
        for (int j = 0; j < 4; j++)
            #pragma unroll
            for (int k = 0; k < 4; k++) c[i][j][k] = 0.f;

    // ldmatrix source addresses (per-lane), computed once
    // A: row = wm + mt*16 + lane%16, col = k + (lane/16)*8
    // B: row = wn + nt2*16 + lane%8 + ((lane/16)*8), col = k + ((lane/8)%2)*8
    const int a_r = wm + (lane & 15);
    const int a_c = (lane >> 4) * 8;
    const int b_r = wn + (lane & 7) + ((lane >> 4) << 3);
    const int b_c = ((lane >> 3) & 1) * 8;

    const int segA[3] = {0, 0, Dm};
    const int segB[3] = {0, Dm, 0};

    for (int sg = 0; sg < 3; sg++) {
        const int ka = segA[sg], kb = segB[sg];
        for (int kt = 0; kt < Dm; kt += 64) {
            // Load 128x64 A and B tiles
            #pragma unroll
            for (int i = 0; i < 4; i++) {
                int idx = tid + i * 256;      // 0..1023 (uint4 units)
                int row = idx >> 3;
                int c8  = (idx & 7) << 3;
                *(uint4*)&As[row][c8] =
                    *(const uint4*)(Acat + (size_t)(bm + row) * KCAT + ka + kt + c8);
                *(uint4*)&Bs[row][c8] =
                    *(const uint4*)(Bcat + (size_t)(bn + row) * KCAT + kb + kt + c8);
            }
            __syncthreads();

            #pragma unroll
            for (int kk = 0; kk < 64; kk += 16) {
                uint32_t a[4][4], b[4][2];
                #pragma unroll
                for (int mt = 0; mt < 4; mt++) {
                    uint32_t ad = s2u(&As[a_r + mt*16][kk + a_c]);
                    LDMAT4(a[mt][0], a[mt][1], a[mt][2], a[mt][3], ad);
                }
                #pragma unroll
                for (int nt2 = 0; nt2 < 2; nt2++) {
                    uint32_t bd = s2u(&Bs[b_r + nt2*16][kk + b_c]);
                    LDMAT4(b[nt2*2][0], b[nt2*2][1], b[nt2*2+1][0], b[nt2*2+1][1], bd);
                }
                #pragma unroll
                for (int mt = 0; mt < 4; mt++)
                    #pragma unroll
                    for (int nt = 0; nt < 4; nt++)
                        MMA16816(c[mt][nt][0], c[mt][nt][1], c[mt][nt][2], c[mt][nt][3],
                                 a[mt][0], a[mt][1], a[mt][2], a[mt][3],
                                 b[nt][0], b[nt][1]);
            }
            __syncthreads();
        }
    }

    // Epilogue
    #pragma unroll
    for (int mt = 0; mt < 4; mt++) {
        #pragma unroll
        for (int nt = 0; nt < 4; nt++) {
            int row0 = bm + wm + mt*16 + (lane >> 2);
            int col  = bn + wn + nt*8 + (lane & 3) * 2;
            float b0 = bias[col], b1 = bias[col + 1];
            float v0 = c[mt][nt][0] + b0;
            float v1 = c[mt][nt][1] + b1;
            float v2 = c[mt][nt][2] + b0;
            float v3 = c[mt][nt][3] + b1;
            if (HAS_RES) {
                const float2 r0 = *(const float2*)(res + (size_t)row0 * Dm + col);
                const float2 r1 = *(const float2*)(res + (size_t)(row0+8) * Dm + col);
                v0 += r0.x; v1 += r0.y; v2 += r1.x; v3 += r1.y;
            }
            *(float2*)(C + (size_t)row0 * Dm + col)     = make_float2(v0, v1);
            *(float2*)(C + (size_t)(row0+8) * Dm + col) = make_float2(v2, v3);
        }
    }
}

// ---------------------------------------------------------------------------
// Flash attention (fp32, online softmax). Unchanged from R1.
// ---------------------------------------------------------------------------
__global__ __launch_bounds__(256) void attn_kernel(const float* __restrict__ ascale)
{
    extern __shared__ float smf[];
    float* Qs = smf;
    float* Ks = smf + 64*68;
    float* Vs = smf + 2*64*68;
    float* Ps = smf + 3*64*68;

    const int q0 = blockIdx.x * 64;
    const int h  = blockIdx.y;
    const int b  = blockIdx.z;
    const int tid = threadIdx.x;
    const int tx = tid & 15, ty = tid >> 4;

    const float sc = ascale[h] * 0.125f;

    #pragma unroll
    for (int t = 0; t < 4; t++) {
        int idx = tid + t*256;
        int row = idx >> 4;
        int c4  = (idx & 15) << 2;
        float4 v = *(const float4*)(g_Q + (size_t)(b*SEQ + q0 + row)*Dm + h*HD + c4);
        Qs[row*68 + c4+0] = v.x; Qs[row*68 + c4+1] = v.y;
        Qs[row*68 + c4+2] = v.z; Qs[row*68 + c4+3] = v.w;
    }

    float m[4], l[4], acc[4][4];
    #pragma unroll
    for (int i = 0; i < 4; i++) {
        m[i] = -INFINITY; l[i] = 0.f;
        #pragma unroll
        for (int j = 0; j < 4; j++) acc[i][j] = 0.f;
    }

    for (int k0 = 0; k0 < SEQ; k0 += 64) {
        #pragma unroll
        for (int t = 0; t < 4; t++) {
            int idx = tid + t*256;
            int row = idx >> 4;
            int c4  = (idx & 15) << 2;
            size_t off = (size_t)(b*SEQ + k0 + row)*Dm + h*HD + c4;
            float4 kv = *(const float4*)(g_K + off);
            float4 vv = *(const float4*)(g_V + off);
            Ks[row*68 + c4+0] = kv.x; Ks[row*68 + c4+1] = kv.y;
            Ks[row*68 + c4+2] = kv.z; Ks[row*68 + c4+3] = kv.w;
            Vs[row*68 + c4+0] = vv.x; Vs[row*68 + c4+1] = vv.y;
            Vs[row*68 + c4+2] = vv.z; Vs[row*68 + c4+3] = vv.w;
        }
        __syncthreads();

        float s[4][4] = {};
        #pragma unroll 16
        for (int d = 0; d < 64; d++) {
            float a[4], bb[4];
            #pragma unroll
            for (int i = 0; i < 4; i++) a[i]  = Qs[(ty*4 + i)*68 + d];
            #pragma unroll
            for (int j = 0; j < 4; j++) bb[j] = Ks[(tx*4 + j)*68 + d];
            #pragma unroll
            for (int i = 0; i < 4; i++)
                #pragma unroll
                for (int j = 0; j < 4; j++)
                    s[i][j] = fmaf(a[i], bb[j], s[i][j]);
        }

        #pragma unroll
        for (int i = 0; i < 4; i++) {
            #pragma unroll
            for (int j = 0; j < 4; j++) s[i][j] *= sc;
            float rm = fmaxf(fmaxf(s[i][0], s[i][1]), fmaxf(s[i][2], s[i][3]));
            #pragma unroll
            for (int off = 8; off; off >>= 1)
                rm = fmaxf(rm, __shfl_xor_sync(0xffffffffu, rm, off));
            float mn = fmaxf(m[i], rm);
            float corr = __expf(m[i] - mn);
            float rs = 0.f;
            #pragma unroll
            for (int j = 0; j < 4; j++) {
                float p = __expf(s[i][j] - mn);
                s[i][j] = p;
                rs += p;
            }
            #pragma unroll
            for (int off = 8; off; off >>= 1)
                rs += __shfl_xor_sync(0xffffffffu, rs, off);
            l[i] = l[i] * corr + rs;
            m[i] = mn;
            #pragma unroll
            for (int j = 0; j < 4; j++) acc[i][j] *= corr;
            #pragma unroll
            for (int j = 0; j < 4; j++)
                Ps[(ty*4 + i)*68 + tx*4 + j] = s[i][j];
        }
        __syncthreads();

        #pragma unroll 16
        for (int k = 0; k < 64; k++) {
            float a[4], bb[4];
            #pragma unroll
            for (int i = 0; i < 4; i++) a[i]  = Ps[(ty*4 + i)*68 + k];
            #pragma unroll
            for (int j = 0; j < 4; j++) bb[j] = Vs[k*68 + tx*4 + j];
            #pragma unroll
            for (int i = 0; i < 4; i++)
                #pragma unroll
                for (int j = 0; j < 4; j++)
                    acc[i][j] = fmaf(a[i], bb[j], acc[i][j]);
        }
        __syncthreads();
    }

    #pragma unroll
    for (int i = 0; i < 4; i++) {
        float inv = 1.f / l[i];
        int row = q0 + ty*4 + i;
        int col = h*HD + tx*4;
        float4 o;
        o.x = acc[i][0]*inv; o.y = acc[i][1]*inv;
        o.z = acc[i][2]*inv; o.w = acc[i][3]*inv;
        *(float4*)(g_A + (size_t)(b*SEQ + row)*Dm + col) = o;
    }
}

// ---------------------------------------------------------------------------
// LayerNorm: one block per row.
// ---------------------------------------------------------------------------
__global__ __launch_bounds__(256) void ln_kernel(
    const float* __restrict__ y, const float* __restrict__ gamma,
    const float* __restrict__ beta, float* __restrict__ out)
{
    __shared__ float red[16];
    __shared__ float mu_s, rstd_s;
    const int row = blockIdx.x;
    const int tid = threadIdx.x;
    const float* yr = y + (size_t)row * Dm;

    float4 v = *(const float4*)(yr + tid*4);
    float s  = v.x + v.y + v.z + v.w;
    float s2 = v.x*v.x + v.y*v.y + v.z*v.z + v.w*v.w;
    #pragma unroll
    for (int off = 16; off; off >>= 1) {
        s  += __shfl_xor_sync(0xffffffffu, s,  off);
        s2 += __shfl_xor_sync(0xffffffffu, s2, off);
    }
    if ((tid & 31) == 0) {
        red[tid >> 5] = s;
        red[8 + (tid >> 5)] = s2;
    }
    __syncthreads();
    if (tid == 0) {
        float S = 0.f, S2 = 0.f;
        #pragma unroll
        for (int w = 0; w < 8; w++) { S += red[w]; S2 += red[8 + w]; }
        float mu = S * (1.f/1024.f);
        float var = S2 * (1.f/1024.f) - mu*mu;
        mu_s = mu;
        rstd_s = rsqrtf(var + 1e-5f);
    }
    __syncthreads();
    const float mu = mu_s, rstd = rstd_s;
    float4 g  = *(const float4*)(gamma + tid*4);
    float4 be = *(const float4*)(beta  + tid*4);
    float4 o;
    o.x = (v.x - mu) * rstd * g.x + be.x;
    o.y = (v.y - mu) * rstd * g.y + be.y;
    o.z = (v.z - mu) * rstd * g.z + be.z;
    o.w = (v.w - mu) * rstd * g.w + be.w;
    *(float4*)(out + (size_t)row * Dm + tid*4) = o;
}

// ---------------------------------------------------------------------------
extern "C" void kernel_launch(void* const* d_in, const int* in_sizes, int n_in,
                              void* d_out, int out_size)
{
    const float* x     = (const float*)d_in[0];
    const float* as    = (const float*)d_in[1];
    const float* Wq    = (const float*)d_in[2];
    const float* bq    = (const float*)d_in[3];
    const float* Wk    = (const float*)d_in[4];
    const float* bk    = (const float*)d_in[5];
    const float* Wv    = (const float*)d_in[6];
    const float* bv    = (const float*)d_in[7];
    const float* Wo    = (const float*)d_in[8];
    const float* bo    = (const float*)d_in[9];
    const float* gamma = (const float*)d_in[10];
    const float* beta  = (const float*)d_in[11];
    float* out = (float*)d_out;

    float *Qp, *Kp, *Vp, *Ap, *Yp;
    __nv_bfloat16 *Xc, *Ac, *Wc;
    cudaGetSymbolAddress((void**)&Qp, g_Q);
    cudaGetSymbolAddress((void**)&Kp, g_K);
    cudaGetSymbolAddress((void**)&Vp, g_V);
    cudaGetSymbolAddress((void**)&Ap, g_A);
    cudaGetSymbolAddress((void**)&Yp, g_Y);
    cudaGetSymbolAddress((void**)&Xc, g_Xcat);
    cudaGetSymbolAddress((void**)&Ac, g_Acat);
    cudaGetSymbolAddress((void**)&Wc, g_Wcat);

    dim3 blk(256);

    // split conversions: x and the four weight matrices
    split_kernel<<<MROWS * (Dm/4) / 256, blk>>>(x, Xc, MROWS);
    split_kernel<<<Dm * (Dm/4) / 256, blk>>>(Wq, Wc + 0*(size_t)Dm*KCAT, Dm);
    split_kernel<<<Dm * (Dm/4) / 256, blk>>>(Wk, Wc + 1*(size_t)Dm*KCAT, Dm);
    split_kernel<<<Dm * (Dm/4) / 256, blk>>>(Wv, Wc + 2*(size_t)Dm*KCAT, Dm);
    split_kernel<<<Dm * (Dm/4) / 256, blk>>>(Wo, Wc + 3*(size_t)Dm*KCAT, Dm);

    dim3 gg(Dm/128, MROWS/128);   // (8, 32)
    hmma_gemm<false><<<gg, blk>>>(Xc, Wc + 0*(size_t)Dm*KCAT, bq, nullptr, Qp);
    hmma_gemm<false><<<gg, blk>>>(Xc, Wc + 1*(size_t)Dm*KCAT, bk, nullptr, Kp);
    hmma_gemm<false><<<gg, blk>>>(Xc, Wc + 2*(size_t)Dm*KCAT, bv, nullptr, Vp);

    size_t smem = 4 * 64 * 68 * sizeof(float);
    cudaFuncSetAttribute(attn_kernel, cudaFuncAttributeMaxDynamicSharedMemorySize, (int)smem);
    attn_kernel<<<dim3(SEQ/64, NH, BB), blk, smem>>>(as);

    split_kernel<<<MROWS * (Dm/4) / 256, blk>>>(Ap, Ac, MROWS);
    hmma_gemm<true><<<gg, blk>>>(Ac, Wc + 3*(size_t)Dm*KCAT, bo, x, Yp);

    ln_kernel<<<MROWS, blk>>>(Yp, gamma, beta, out);
}

// round 5
// speedup vs baseline: 3.8325x; 3.1291x over previous
#include <cuda_runtime.h>
#include <cuda_bf16.h>
#include <cuda_fp16.h>
#include <cstdint>
#include <math.h>

#define Dm 1024
#define NH 16
#define HD 64
#define BB 2
#define SEQ 2048
#define MROWS (BB*SEQ)   // 4096
#define KCAT 2048        // [hi | lo] concatenated K

// Scratch (alloc-free rule: __device__ globals)
__device__ float g_Y[MROWS*Dm];
__device__ __half g_Qh[(size_t)MROWS*Dm];
__device__ __half g_Kh[(size_t)MROWS*Dm];
__device__ __half g_Vh[(size_t)MROWS*Dm];
__device__ __nv_bfloat16 g_Xcat[(size_t)MROWS*KCAT];
__device__ __nv_bfloat16 g_Acat[(size_t)MROWS*KCAT];
__device__ __nv_bfloat16 g_Wcat[4][(size_t)Dm*KCAT];

__device__ __forceinline__ uint32_t s2u(const void* p) {
    uint32_t a;
    asm("{ .reg .u64 t; cvta.to.shared.u64 t, %1; cvt.u32.u64 %0, t; }" : "=r"(a) : "l"(p));
    return a;
}

// ---------------------------------------------------------------------------
// split fp32 -> [bf16 hi | bf16 lo] concatenated along K
// ---------------------------------------------------------------------------
__global__ __launch_bounds__(256) void split_kernel(
    const float* __restrict__ src, __nv_bfloat16* __restrict__ dst, int nrows)
{
    int idx = blockIdx.x * 256 + threadIdx.x;      // float4 units
    int total = nrows * (Dm / 4);
    if (idx >= total) return;
    int r  = idx / (Dm / 4);
    int c  = (idx % (Dm / 4)) * 4;
    float4 v = *(const float4*)(src + (size_t)r * Dm + c);
    __nv_bfloat16 h0 = __float2bfloat16(v.x);
    __nv_bfloat16 h1 = __float2bfloat16(v.y);
    __nv_bfloat16 h2 = __float2bfloat16(v.z);
    __nv_bfloat16 h3 = __float2bfloat16(v.w);
    __nv_bfloat16 l0 = __float2bfloat16(v.x - __bfloat162float(h0));
    __nv_bfloat16 l1 = __float2bfloat16(v.y - __bfloat162float(h1));
    __nv_bfloat16 l2 = __float2bfloat16(v.z - __bfloat162float(h2));
    __nv_bfloat16 l3 = __float2bfloat16(v.w - __bfloat162float(h3));
    __nv_bfloat162* dh = (__nv_bfloat162*)(dst + (size_t)r * KCAT + c);
    __nv_bfloat162* dl = (__nv_bfloat162*)(dst + (size_t)r * KCAT + Dm + c);
    dh[0] = __nv_bfloat162(h0, h1);
    dh[1] = __nv_bfloat162(h2, h3);
    dl[0] = __nv_bfloat162(l0, l1);
    dl[1] = __nv_bfloat162(l2, l3);
}

// ---------------------------------------------------------------------------
// mma / ldmatrix macros
// ---------------------------------------------------------------------------
#define LDMAT4(r0,r1,r2,r3,addr) \
    asm volatile("ldmatrix.sync.aligned.m8n8.x4.shared.b16 {%0,%1,%2,%3}, [%4];" \
        : "=r"(r0),"=r"(r1),"=r"(r2),"=r"(r3) : "r"(addr))

#define LDMAT4T(r0,r1,r2,r3,addr) \
    asm volatile("ldmatrix.sync.aligned.m8n8.x4.trans.shared.b16 {%0,%1,%2,%3}, [%4];" \
        : "=r"(r0),"=r"(r1),"=r"(r2),"=r"(r3) : "r"(addr))

#define MMA_BF16(c0,c1,c2,c3,a0,a1,a2,a3,b0,b1) \
    asm volatile("mma.sync.aligned.m16n8k16.row.col.f32.bf16.bf16.f32 " \
        "{%0,%1,%2,%3}, {%4,%5,%6,%7}, {%8,%9}, {%0,%1,%2,%3};" \
        : "+f"(c0),"+f"(c1),"+f"(c2),"+f"(c3) \
        : "r"(a0),"r"(a1),"r"(a2),"r"(a3),"r"(b0),"r"(b1))

#define MMA_F16(c0,c1,c2,c3,a0,a1,a2,a3,b0,b1) \
    asm volatile("mma.sync.aligned.m16n8k16.row.col.f32.f16.f16.f32 " \
        "{%0,%1,%2,%3}, {%4,%5,%6,%7}, {%8,%9}, {%0,%1,%2,%3};" \
        : "+f"(c0),"+f"(c1),"+f"(c2),"+f"(c3) \
        : "r"(a0),"r"(a1),"r"(a2),"r"(a3),"r"(b0),"r"(b1))

// ---------------------------------------------------------------------------
// HMMA (mma.sync m16n8k16 bf16) GEMM, 3-segment hi/lo split.
// MODE 0: write fp16 QKV head-major ([B,H,N,64]) with optional per-head scale.
// MODE 1: write fp32 row-major + bias + residual.
// 128x128 CTA tile, 8 warps of 64x32, BK=64.
// ---------------------------------------------------------------------------
template<int MODE>
__global__ __launch_bounds__(256) void hmma_gemm(
    const __nv_bfloat16* __restrict__ Acat, const __nv_bfloat16* __restrict__ Bcat,
    const float* __restrict__ bias, const float* __restrict__ res,
    float* __restrict__ Cf, __half* __restrict__ Ch,
    const float* __restrict__ qscale)
{
    __shared__ __align__(16) __nv_bfloat16 As[128][72];
    __shared__ __align__(16) __nv_bfloat16 Bs[128][72];

    const int tid  = threadIdx.x;
    const int wid  = tid >> 5, lane = tid & 31;
    const int bm = blockIdx.y * 128;
    const int bn = blockIdx.x * 128;
    const int wm = (wid >> 2) * 64;
    const int wn = (wid & 3) * 32;

    float c[4][4][4];
    #pragma unroll
    for (int i = 0; i < 4; i++)
        #pragma unroll
        for (int j = 0; j < 4; j++)
            #pragma unroll
            for (int k = 0; k < 4; k++) c[i][j][k] = 0.f;

    const int a_r = wm + (lane & 15);
    const int a_c = (lane >> 4) * 8;
    const int b_r = wn + (lane & 7) + ((lane >> 4) << 3);
    const int b_c = ((lane >> 3) & 1) * 8;

    const int segA[3] = {0, 0, Dm};
    const int segB[3] = {0, Dm, 0};

    for (int sg = 0; sg < 3; sg++) {
        const int ka = segA[sg], kb = segB[sg];
        for (int kt = 0; kt < Dm; kt += 64) {
            #pragma unroll
            for (int i = 0; i < 4; i++) {
                int idx = tid + i * 256;
                int row = idx >> 3;
                int c8  = (idx & 7) << 3;
                *(uint4*)&As[row][c8] =
                    *(const uint4*)(Acat + (size_t)(bm + row) * KCAT + ka + kt + c8);
                *(uint4*)&Bs[row][c8] =
                    *(const uint4*)(Bcat + (size_t)(bn + row) * KCAT + kb + kt + c8);
            }
            __syncthreads();

            #pragma unroll
            for (int kk = 0; kk < 64; kk += 16) {
                uint32_t a[4][4], b[4][2];
                #pragma unroll
                for (int mt = 0; mt < 4; mt++) {
                    uint32_t ad = s2u(&As[a_r + mt*16][kk + a_c]);
                    LDMAT4(a[mt][0], a[mt][1], a[mt][2], a[mt][3], ad);
                }
                #pragma unroll
                for (int nt2 = 0; nt2 < 2; nt2++) {
                    uint32_t bd = s2u(&Bs[b_r + nt2*16][kk + b_c]);
                    LDMAT4(b[nt2*2][0], b[nt2*2][1], b[nt2*2+1][0], b[nt2*2+1][1], bd);
                }
                #pragma unroll
                for (int mt = 0; mt < 4; mt++)
                    #pragma unroll
                    for (int nt = 0; nt < 4; nt++)
                        MMA_BF16(c[mt][nt][0], c[mt][nt][1], c[mt][nt][2], c[mt][nt][3],
                                 a[mt][0], a[mt][1], a[mt][2], a[mt][3],
                                 b[nt][0], b[nt][1]);
            }
            __syncthreads();
        }
    }

    // Epilogue
    #pragma unroll
    for (int mt = 0; mt < 4; mt++) {
        #pragma unroll
        for (int nt = 0; nt < 4; nt++) {
            int row0 = bm + wm + mt*16 + (lane >> 2);
            int col  = bn + wn + nt*8 + (lane & 3) * 2;
            float b0 = bias[col], b1 = bias[col + 1];
            float v0 = c[mt][nt][0] + b0;
            float v1 = c[mt][nt][1] + b1;
            float v2 = c[mt][nt][2] + b0;
            float v3 = c[mt][nt][3] + b1;
            if (MODE == 1) {
                const float2 r0 = *(const float2*)(res + (size_t)row0 * Dm + col);
                const float2 r1 = *(const float2*)(res + (size_t)(row0+8) * Dm + col);
                v0 += r0.x; v1 += r0.y; v2 += r1.x; v3 += r1.y;
                *(float2*)(Cf + (size_t)row0 * Dm + col)     = make_float2(v0, v1);
                *(float2*)(Cf + (size_t)(row0+8) * Dm + col) = make_float2(v2, v3);
            } else {
                // head-major fp16 write with optional per-head scale
                float qs = 1.f;
                if (qscale) qs = qscale[col >> 6] * 0.180336880f; // 0.125*log2(e)
                int b  = row0 >> 11;
                int n0 = row0 & 2047;
                int h  = col >> 6;
                int d  = col & 63;
                __half* base = Ch + (((size_t)(b * NH + h) * SEQ)) * HD + d;
                *(__half2*)(base + (size_t)n0 * HD)     = __floats2half2_rn(v0*qs, v1*qs);
                *(__half2*)(base + (size_t)(n0+8) * HD) = __floats2half2_rn(v2*qs, v3*qs);
            }
        }
    }
}

// ---------------------------------------------------------------------------
// Flash attention, fp16 HMMA, online softmax in log2 domain.
// CTA: 128 queries, 8 warps (16 rows each), KV tiles of 64.
// Q pre-scaled by ascale*0.125*log2(e) -> mma output is exp2 argument.
// Epilogue writes bf16 hi/lo directly into g_Acat.
// ---------------------------------------------------------------------------
__global__ __launch_bounds__(256) void attn_kernel()
{
    __shared__ __align__(16) __half Qs[128][72];
    __shared__ __align__(16) __half Ks[64][72];
    __shared__ __align__(16) __half Vs[64][72];

    const int tid = threadIdx.x;
    const int wid = tid >> 5, lane = tid & 31;
    const int q0 = blockIdx.x * 128;
    const int bh = blockIdx.y;              // b*NH + h

    const __half* Qg = g_Qh + (size_t)bh * SEQ * HD;
    const __half* Kg = g_Kh + (size_t)bh * SEQ * HD;
    const __half* Vg = g_Vh + (size_t)bh * SEQ * HD;

    // load Q tile 128x64
    #pragma unroll
    for (int i = 0; i < 4; i++) {
        int idx = tid + i * 256;
        int row = idx >> 3;
        int c8  = (idx & 7) << 3;
        *(uint4*)&Qs[row][c8] = *(const uint4*)(Qg + (size_t)(q0 + row) * HD + c8);
    }
    __syncthreads();

    // preload Q fragments (Qs is never overwritten)
    const int a_r = wid * 16 + (lane & 15);
    const int a_c = (lane >> 4) * 8;
    uint32_t aq[4][4];
    #pragma unroll
    for (int kc = 0; kc < 4; kc++) {
        uint32_t ad = s2u(&Qs[a_r][kc*16 + a_c]);
        LDMAT4(aq[kc][0], aq[kc][1], aq[kc][2], aq[kc][3], ad);
    }

    const int b_r = (lane & 7) + ((lane >> 4) << 3);
    const int b_c = ((lane >> 3) & 1) * 8;
    const int v_r = (lane & 15);
    const int v_c = (lane >> 4) << 3;

    float o[8][4];
    #pragma unroll
    for (int i = 0; i < 8; i++)
        #pragma unroll
        for (int j = 0; j < 4; j++) o[i][j] = 0.f;
    float m0 = -1e30f, m1 = -1e30f, l0 = 0.f, l1 = 0.f;

    for (int k0 = 0; k0 < SEQ; k0 += 64) {
        // load K,V tiles (64x64 each)
        #pragma unroll
        for (int i = 0; i < 2; i++) {
            int idx = tid + i * 256;
            int row = idx >> 3;
            int c8  = (idx & 7) << 3;
            *(uint4*)&Ks[row][c8] = *(const uint4*)(Kg + (size_t)(k0 + row) * HD + c8);
            *(uint4*)&Vs[row][c8] = *(const uint4*)(Vg + (size_t)(k0 + row) * HD + c8);
        }
        __syncthreads();

        // S = Q @ K^T (already scaled to log2 domain)
        float c[8][4];
        #pragma unroll
        for (int i = 0; i < 8; i++)
            #pragma unroll
            for (int j = 0; j < 4; j++) c[i][j] = 0.f;
        #pragma unroll
        for (int kk = 0; kk < 4; kk++) {
            uint32_t bf[8][2];
            #pragma unroll
            for (int nt2 = 0; nt2 < 4; nt2++) {
                uint32_t bd = s2u(&Ks[b_r + nt2*16][kk*16 + b_c]);
                LDMAT4(bf[nt2*2][0], bf[nt2*2][1], bf[nt2*2+1][0], bf[nt2*2+1][1], bd);
            }
            #pragma unroll
            for (int nt = 0; nt < 8; nt++)
                MMA_F16(c[nt][0], c[nt][1], c[nt][2], c[nt][3],
                        aq[kk][0], aq[kk][1], aq[kk][2], aq[kk][3],
                        bf[nt][0], bf[nt][1]);
        }

        // online softmax (log2 domain)
        float rm0 = c[0][0], rm1 = c[0][2];
        #pragma unroll
        for (int nt = 0; nt < 8; nt++) {
            rm0 = fmaxf(rm0, fmaxf(c[nt][0], c[nt][1]));
            rm1 = fmaxf(rm1, fmaxf(c[nt][2], c[nt][3]));
        }
        rm0 = fmaxf(rm0, __shfl_xor_sync(0xffffffffu, rm0, 1));
        rm0 = fmaxf(rm0, __shfl_xor_sync(0xffffffffu, rm0, 2));
        rm1 = fmaxf(rm1, __shfl_xor_sync(0xffffffffu, rm1, 1));
        rm1 = fmaxf(rm1, __shfl_xor_sync(0xffffffffu, rm1, 2));
        float mn0 = fmaxf(m0, rm0);
        float mn1 = fmaxf(m1, rm1);
        float corr0 = exp2f(m0 - mn0);
        float corr1 = exp2f(m1 - mn1);
        m0 = mn0; m1 = mn1;

        __half2 p2[8][2];
        #pragma unroll
        for (int nt = 0; nt < 8; nt++) {
            p2[nt][0] = h2exp2(__floats2half2_rn(c[nt][0] - m0, c[nt][1] - m0));
            p2[nt][1] = h2exp2(__floats2half2_rn(c[nt][2] - m1, c[nt][3] - m1));
        }

        __half2 s20 = p2[0][0], s21 = p2[0][1];
        #pragma unroll
        for (int nt = 1; nt < 8; nt++) {
            s20 = __hadd2(s20, p2[nt][0]);
            s21 = __hadd2(s21, p2[nt][1]);
        }
        float s0 = __low2float(s20) + __high2float(s20);
        float s1 = __low2float(s21) + __high2float(s21);
        s0 += __shfl_xor_sync(0xffffffffu, s0, 1);
        s0 += __shfl_xor_sync(0xffffffffu, s0, 2);
        s1 += __shfl_xor_sync(0xffffffffu, s1, 1);
        s1 += __shfl_xor_sync(0xffffffffu, s1, 2);
        l0 = l0 * corr0 + s0;
        l1 = l1 * corr1 + s1;

        #pragma unroll
        for (int nt = 0; nt < 8; nt++) {
            o[nt][0] *= corr0; o[nt][1] *= corr0;
            o[nt][2] *= corr1; o[nt][3] *= corr1;
        }

        // O += P @ V  (V via ldmatrix.trans)
        #pragma unroll
        for (int kc = 0; kc < 4; kc++) {
            uint32_t pa0 = *(uint32_t*)&p2[2*kc][0];
            uint32_t pa1 = *(uint32_t*)&p2[2*kc][1];
            uint32_t pa2 = *(uint32_t*)&p2[2*kc+1][0];
            uint32_t pa3 = *(uint32_t*)&p2[2*kc+1][1];
            #pragma unroll
            for (int dg = 0; dg < 4; dg++) {
                uint32_t v0, v1, v2, v3;
                uint32_t vd = s2u(&Vs[kc*16 + v_r][dg*16 + v_c]);
                LDMAT4T(v0, v1, v2, v3, vd);
                MMA_F16(o[dg*2][0], o[dg*2][1], o[dg*2][2], o[dg*2][3],
                        pa0, pa1, pa2, pa3, v0, v1);
                MMA_F16(o[dg*2+1][0], o[dg*2+1][1], o[dg*2+1][2], o[dg*2+1][3],
                        pa0, pa1, pa2, pa3, v2, v3);
            }
        }
        __syncthreads();
    }

    // epilogue: write bf16 hi/lo into g_Acat
    const float inv0 = 1.f / l0;
    const float inv1 = 1.f / l1;
    const int b = bh >> 4, h = bh & 15;
    const int r0 = q0 + wid * 16 + (lane >> 2);
    const size_t tok0 = (size_t)b * SEQ + r0;
    #pragma unroll
    for (int nt = 0; nt < 8; nt++) {
        int col = h * HD + nt * 8 + (lane & 3) * 2;
        float v0 = o[nt][0] * inv0, v1 = o[nt][1] * inv0;
        float v2 = o[nt][2] * inv1, v3 = o[nt][3] * inv1;
        __nv_bfloat16 h0 = __float2bfloat16(v0), h1 = __float2bfloat16(v1);
        __nv_bfloat16 h2 = __float2bfloat16(v2), h3 = __float2bfloat16(v3);
        __nv_bfloat16 e0 = __float2bfloat16(v0 - __bfloat162float(h0));
        __nv_bfloat16 e1 = __float2bfloat16(v1 - __bfloat162float(h1));
        __nv_bfloat16 e2 = __float2bfloat16(v2 - __bfloat162float(h2));
        __nv_bfloat16 e3 = __float2bfloat16(v3 - __bfloat162float(h3));
        *(__nv_bfloat162*)&g_Acat[tok0 * KCAT + col]            = __nv_bfloat162(h0, h1);
        *(__nv_bfloat162*)&g_Acat[tok0 * KCAT + Dm + col]       = __nv_bfloat162(e0, e1);
        *(__nv_bfloat162*)&g_Acat[(tok0+8) * KCAT + col]        = __nv_bfloat162(h2, h3);
        *(__nv_bfloat162*)&g_Acat[(tok0+8) * KCAT + Dm + col]   = __nv_bfloat162(e2, e3);
    }
}

// ---------------------------------------------------------------------------
// LayerNorm: one block per row.
// ---------------------------------------------------------------------------
__global__ __launch_bounds__(256) void ln_kernel(
    const float* __restrict__ y, const float* __restrict__ gamma,
    const float* __restrict__ beta, float* __restrict__ out)
{
    __shared__ float red[16];
    __shared__ float mu_s, rstd_s;
    const int row = blockIdx.x;
    const int tid = threadIdx.x;
    const float* yr = y + (size_t)row * Dm;

    float4 v = *(const float4*)(yr + tid*4);
    float s  = v.x + v.y + v.z + v.w;
    float s2 = v.x*v.x + v.y*v.y + v.z*v.z + v.w*v.w;
    #pragma unroll
    for (int off = 16; off; off >>= 1) {
        s  += __shfl_xor_sync(0xffffffffu, s,  off);
        s2 += __shfl_xor_sync(0xffffffffu, s2, off);
    }
    if ((tid & 31) == 0) {
        red[tid >> 5] = s;
        red[8 + (tid >> 5)] = s2;
    }
    __syncthreads();
    if (tid == 0) {
        float S = 0.f, S2 = 0.f;
        #pragma unroll
        for (int w = 0; w < 8; w++) { S += red[w]; S2 += red[8 + w]; }
        float mu = S * (1.f/1024.f);
        float var = S2 * (1.f/1024.f) - mu*mu;
        mu_s = mu;
        rstd_s = rsqrtf(var + 1e-5f);
    }
    __syncthreads();
    const float mu = mu_s, rstd = rstd_s;
    float4 g  = *(const float4*)(gamma + tid*4);
    float4 be = *(const float4*)(beta  + tid*4);
    float4 o;
    o.x = (v.x - mu) * rstd * g.x + be.x;
    o.y = (v.y - mu) * rstd * g.y + be.y;
    o.z = (v.z - mu) * rstd * g.z + be.z;
    o.w = (v.w - mu) * rstd * g.w + be.w;
    *(float4*)(out + (size_t)row * Dm + tid*4) = o;
}

// ---------------------------------------------------------------------------
extern "C" void kernel_launch(void* const* d_in, const int* in_sizes, int n_in,
                              void* d_out, int out_size)
{
    const float* x     = (const float*)d_in[0];
    const float* as    = (const float*)d_in[1];
    const float* Wq    = (const float*)d_in[2];
    const float* bq    = (const float*)d_in[3];
    const float* Wk    = (const float*)d_in[4];
    const float* bk    = (const float*)d_in[5];
    const float* Wv    = (const float*)d_in[6];
    const float* bv    = (const float*)d_in[7];
    const float* Wo    = (const float*)d_in[8];
    const float* bo    = (const float*)d_in[9];
    const float* gamma = (const float*)d_in[10];
    const float* beta  = (const float*)d_in[11];
    float* out = (float*)d_out;

    float *Yp;
    __half *Qh, *Kh, *Vh;
    __nv_bfloat16 *Xc, *Ac, *Wc;
    cudaGetSymbolAddress((void**)&Yp, g_Y);
    cudaGetSymbolAddress((void**)&Qh, g_Qh);
    cudaGetSymbolAddress((void**)&Kh, g_Kh);
    cudaGetSymbolAddress((void**)&Vh, g_Vh);
    cudaGetSymbolAddress((void**)&Xc, g_Xcat);
    cudaGetSymbolAddress((void**)&Ac, g_Acat);
    cudaGetSymbolAddress((void**)&Wc, g_Wcat);

    dim3 blk(256);

    // split conversions: x and the four weight matrices
    split_kernel<<<MROWS * (Dm/4) / 256, blk>>>(x, Xc, MROWS);
    split_kernel<<<Dm * (Dm/4) / 256, blk>>>(Wq, Wc + 0*(size_t)Dm*KCAT, Dm);
    split_kernel<<<Dm * (Dm/4) / 256, blk>>>(Wk, Wc + 1*(size_t)Dm*KCAT, Dm);
    split_kernel<<<Dm * (Dm/4) / 256, blk>>>(Wv, Wc + 2*(size_t)Dm*KCAT, Dm);
    split_kernel<<<Dm * (Dm/4) / 256, blk>>>(Wo, Wc + 3*(size_t)Dm*KCAT, Dm);

    dim3 gg(Dm/128, MROWS/128);   // (8, 32)
    hmma_gemm<0><<<gg, blk>>>(Xc, Wc + 0*(size_t)Dm*KCAT, bq, nullptr, nullptr, Qh, as);
    hmma_gemm<0><<<gg, blk>>>(Xc, Wc + 1*(size_t)Dm*KCAT, bk, nullptr, nullptr, Kh, nullptr);
    hmma_gemm<0><<<gg, blk>>>(Xc, Wc + 2*(size_t)Dm*KCAT, bv, nullptr, nullptr, Vh, nullptr);

    attn_kernel<<<dim3(SEQ/128, NH*BB), blk>>>();

    hmma_gemm<1><<<gg, blk>>>(Ac, Wc + 3*(size_t)Dm*KCAT, bo, x, Yp, nullptr, nullptr);

    ln_kernel<<<MROWS, blk>>>(Yp, gamma, beta, out);
}